// round 10
// baseline (speedup 1.0000x reference)
#include <cuda_runtime.h>
#include <math.h>

#define NJ    400000
#define F     128
#define NBLK  148               // 1 block/SM, one wave
#define TPB   128
#define WPB   4
#define NWT   (NBLK * WPB)      // 592 warps
#define NT    (NJ / 32)         // 12500 tiles of 32 rows (NJ % 32 == 0)
#define RS    132               // smem row stride in floats (conflict-free, 16B-mult)
#define TILE_F (32 * RS)        // 4224 floats per tile buffer
#define DEPTH 3
#define DYN_SMEM (WPB * DEPTH * TILE_F * 4)   // 202752 bytes

// Scratch (allocation-free rule: __device__ globals)
__device__ float g_pv[8 * F];
__device__ float g_c0;
__device__ float g_m[NBLK];
__device__ float g_s[NBLK];
__device__ float g_u[NBLK * F];
__device__ unsigned int g_cnt;

// ---------------------------------------------------------------------------
// Kernel A: precompute (proven, ~3us).
// ---------------------------------------------------------------------------
__global__ void __launch_bounds__(1024) prep_kernel(
        const float* __restrict__ h_i,
        const float* __restrict__ W_i_w,
        const float* __restrict__ W_i_b,
        const float* __restrict__ W_j_w,
        const float* __restrict__ W_j_b,
        const float* __restrict__ W_ij) {
    const int tid  = threadIdx.x;
    const int b    = blockIdx.x;

    if (b < 8) {
        __shared__ float s_p[8 * F];
        const int t   = tid & 127;
        const int sub = tid >> 7;
        const int f0  = b * 16 + sub * 2;
        float acc = W_j_w[f0 * F + t]       * W_ij[F + f0]
                  + W_j_w[(f0 + 1) * F + t] * W_ij[F + f0 + 1];
        s_p[sub * F + t] = acc;
        __syncthreads();
        if (tid < F) {
            float v = 0.f;
#pragma unroll
            for (int s = 0; s < 8; s++) v += s_p[s * F + tid];
            g_pv[b * F + tid] = v;
        }
        return;
    }

    __shared__ __align__(16) float s_hi[F];
    __shared__ float s_z[F];
    __shared__ float s_red[F];
    const int wid  = tid >> 5;
    const int lane = tid & 31;

    if (tid == 0) g_cnt = 0u;
    if (tid < F) s_hi[tid] = h_i[tid];
    __syncthreads();

    const float4 hv = reinterpret_cast<const float4*>(s_hi)[lane];
    const float4 w0 = reinterpret_cast<const float4*>(W_i_w + (wid      ) * F)[lane];
    const float4 w1 = reinterpret_cast<const float4*>(W_i_w + (wid + 32 ) * F)[lane];
    const float4 w2 = reinterpret_cast<const float4*>(W_i_w + (wid + 64 ) * F)[lane];
    const float4 w3 = reinterpret_cast<const float4*>(W_i_w + (wid + 96 ) * F)[lane];
    float d0 = w0.x*hv.x + w0.y*hv.y + w0.z*hv.z + w0.w*hv.w;
    float d1 = w1.x*hv.x + w1.y*hv.y + w1.z*hv.z + w1.w*hv.w;
    float d2 = w2.x*hv.x + w2.y*hv.y + w2.z*hv.z + w2.w*hv.w;
    float d3 = w3.x*hv.x + w3.y*hv.y + w3.z*hv.z + w3.w*hv.w;
#pragma unroll
    for (int off = 16; off > 0; off >>= 1) {
        d0 += __shfl_xor_sync(0xffffffffu, d0, off);
        d1 += __shfl_xor_sync(0xffffffffu, d1, off);
        d2 += __shfl_xor_sync(0xffffffffu, d2, off);
        d3 += __shfl_xor_sync(0xffffffffu, d3, off);
    }
    if (lane == 0) {
        s_z[wid     ] = d0 + W_i_b[wid     ];
        s_z[wid + 32] = d1 + W_i_b[wid + 32];
        s_z[wid + 64] = d2 + W_i_b[wid + 64];
        s_z[wid + 96] = d3 + W_i_b[wid + 96];
    }
    __syncthreads();

    if (tid < F) s_red[tid] = W_ij[tid] * s_z[tid] + W_j_b[tid] * W_ij[F + tid];
    __syncthreads();
    if (tid < 64) s_red[tid] += s_red[tid + 64];
    __syncthreads();
    if (tid < 32) {
        float c = s_red[tid] + s_red[tid + 32];
#pragma unroll
        for (int off = 16; off > 0; off >>= 1)
            c += __shfl_xor_sync(0xffffffffu, c, off);
        if (tid == 0) g_c0 = c;
    }
}

// ---------------------------------------------------------------------------
__device__ __forceinline__ void cp16(void* dst, const void* src) {
    unsigned d = (unsigned)__cvta_generic_to_shared(dst);
    asm volatile("cp.async.cg.shared.global [%0], [%1], 16;"
                 :: "r"(d), "l"(src) : "memory");
}
__device__ __forceinline__ void cp_commit() {
    asm volatile("cp.async.commit_group;" ::: "memory");
}

// ---------------------------------------------------------------------------
// Kernel B: smem-staged streaming pass + fused finalize.
// Per warp: 32-row tiles via cp.async (3-deep ring). Lane = one row's logit
// (no shuffles in dot); one exp per lane per tile; u accumulated column-wise.
// ---------------------------------------------------------------------------
__global__ void __launch_bounds__(TPB) pass_kernel(
        const float* __restrict__ h_j,
        const float* __restrict__ W_j_w,
        const float* __restrict__ W_j_b,
        float* __restrict__ out) {
    extern __shared__ __align__(16) float smem_tiles[];   // [WPB][DEPTH][TILE_F]
    __shared__ __align__(16) float sv[F];
    __shared__ float s_w[WPB * 32];
    __shared__ float red_m[WPB];
    __shared__ float red_s[WPB];
    __shared__ float red_u[WPB * F];
    __shared__ float s_mb;

    const int tid  = threadIdx.x;
    const int warp = tid >> 5;
    const int lane = tid & 31;

    if (tid < F) {
        float v = 0.f;
#pragma unroll
        for (int s = 0; s < 8; s++) v += g_pv[s * F + tid];
        sv[tid] = v;
    }
    __syncthreads();

    const float c0 = g_c0;
    float* tb = smem_tiles + warp * (DEPTH * TILE_F);
    const int t0 = blockIdx.x * WPB + warp;   // first tile id for this warp

    // prime: tiles t0 (slot 0) and t0+NWT (slot 1). Both always exist
    // (t0 <= 591, t0+NWT <= 1183 < NT=12500).
    {
        const float* src = h_j + (size_t)t0 * 32 * F + lane * 4;
        float* dst = tb + lane * 4;
#pragma unroll
        for (int i = 0; i < 32; i++) cp16(dst + i * RS, src + i * F);
        cp_commit();
        const float* src1 = h_j + (size_t)(t0 + NWT) * 32 * F + lane * 4;
        float* dst1 = tb + TILE_F + lane * 4;
#pragma unroll
        for (int i = 0; i < 32; i++) cp16(dst1 + i * RS, src1 + i * F);
        cp_commit();
    }

    float m = -1e30f, ssum = 0.f;
    float u0 = 0.f, u1 = 0.f, u2 = 0.f, u3 = 0.f;

    int slot = 0;
    for (int t = t0; t < NT; t += NWT) {
        __syncwarp();   // all lanes done reading the buffer being overwritten
        const bool has1 = (t + NWT)     < NT;
        const bool has2 = (t + 2 * NWT) < NT;
        if (has2) {
            const int ns = (slot + 2) % 3;
            const float* src = h_j + (size_t)(t + 2 * NWT) * 32 * F + lane * 4;
            float* dst = tb + ns * TILE_F + lane * 4;
#pragma unroll
            for (int i = 0; i < 32; i++) cp16(dst + i * RS, src + i * F);
            cp_commit();
            asm volatile("cp.async.wait_group 2;" ::: "memory");
        } else if (has1) {
            asm volatile("cp.async.wait_group 1;" ::: "memory");
        } else {
            asm volatile("cp.async.wait_group 0;" ::: "memory");
        }
        __syncwarp();

        const float* tile = tb + slot * TILE_F;

        // dot: lane's own row, straight from smem (conflict-free), no shuffles
        const float4* myrow = reinterpret_cast<const float4*>(tile + lane * RS);
        const float4* v4    = reinterpret_cast<const float4*>(sv);
        float d = 0.f;
#pragma unroll
        for (int k = 0; k < 32; k++) {
            const float4 a  = myrow[k];
            const float4 vv = v4[k];
            d += a.x*vv.x + a.y*vv.y + a.z*vv.z + a.w*vv.w;
        }
        const float s = d + c0;
        const float e = (s > 0.f) ? s : 0.1f * s;

        // tile max (5 shuffles per 32 rows)
        float mt = e;
#pragma unroll
        for (int off = 16; off > 0; off >>= 1)
            mt = fmaxf(mt, __shfl_xor_sync(0xffffffffu, mt, off));

        if (mt > m) {   // warp-uniform
            const float sc = __expf(m - mt);
            ssum *= sc; u0 *= sc; u1 *= sc; u2 *= sc; u3 *= sc;
            m = mt;
        }
        const float w = __expf(e - m);   // one exp per lane per tile
        ssum += w;                        // per-lane partial sum
        s_w[warp * 32 + lane] = w;
        __syncwarp();

        // accumulate u: lane owns features [4*lane, 4*lane+4)
#pragma unroll
        for (int r = 0; r < 32; r++) {
            const float wr = s_w[warp * 32 + r];                     // broadcast
            const float4 x = *reinterpret_cast<const float4*>(tile + r * RS + lane * 4);
            u0 += wr * x.x; u1 += wr * x.y; u2 += wr * x.z; u3 += wr * x.w;
        }
        slot = (slot + 1) % 3;
    }

    // per-lane ssum -> warp ssum
#pragma unroll
    for (int off = 16; off > 0; off >>= 1)
        ssum += __shfl_xor_sync(0xffffffffu, ssum, off);

    // ---- block combine (4 warps) ----
    if (lane == 0) { red_m[warp] = m; red_s[warp] = ssum; }
    red_u[warp * F + lane * 4 + 0] = u0;
    red_u[warp * F + lane * 4 + 1] = u1;
    red_u[warp * F + lane * 4 + 2] = u2;
    red_u[warp * F + lane * 4 + 3] = u3;
    __syncthreads();

    if (tid == 0) {
        float mb = red_m[0];
#pragma unroll
        for (int w2 = 1; w2 < WPB; w2++) mb = fmaxf(mb, red_m[w2]);
        s_mb = mb;
    }
    __syncthreads();
    const float mb = s_mb;

    {
        float acc = 0.f;
#pragma unroll
        for (int w2 = 0; w2 < WPB; w2++)
            acc += __expf(red_m[w2] - mb) * red_u[w2 * F + tid];
        g_u[blockIdx.x * F + tid] = acc;
    }
    if (tid == 0) {
        float sb = 0.f;
#pragma unroll
        for (int w2 = 0; w2 < WPB; w2++) sb += __expf(red_m[w2] - mb) * red_s[w2];
        g_s[blockIdx.x] = sb;
        g_m[blockIdx.x] = mb;
    }
    __syncthreads();

    // ---- last-block fused finalize ----
    __shared__ unsigned int s_last;
    __threadfence();
    if (tid == 0)
        s_last = (atomicAdd(&g_cnt, 1u) == (unsigned)(NBLK - 1)) ? 1u : 0u;
    __syncthreads();
    if (!s_last) return;

    __shared__ float sf[NBLK];
    __shared__ __align__(16) float sun[F];
    __shared__ float s_r[WPB];
    __shared__ float s_mg, s_S;

    // global max over 148 block maxima
    {
        float lm = -1e30f;
        for (int b = tid; b < NBLK; b += TPB) lm = fmaxf(lm, g_m[b]);
#pragma unroll
        for (int off = 16; off > 0; off >>= 1)
            lm = fmaxf(lm, __shfl_xor_sync(0xffffffffu, lm, off));
        if (lane == 0) s_r[warp] = lm;
        __syncthreads();
        if (tid == 0) {
            float v = s_r[0];
#pragma unroll
            for (int w2 = 1; w2 < WPB; w2++) v = fmaxf(v, s_r[w2]);
            s_mg = v;
        }
        __syncthreads();
    }
    const float mg = s_mg;

    {
        float ls = 0.f;
        for (int b = tid; b < NBLK; b += TPB) {
            const float fct = __expf(g_m[b] - mg);
            sf[b] = fct;
            ls += fct * g_s[b];
        }
#pragma unroll
        for (int off = 16; off > 0; off >>= 1)
            ls += __shfl_xor_sync(0xffffffffu, ls, off);
        if (lane == 0) s_r[warp] = ls;
        __syncthreads();
        if (tid == 0) {
            float v = 0.f;
#pragma unroll
            for (int w2 = 0; w2 < WPB; w2++) v += s_r[w2];
            s_S = v;
        }
        __syncthreads();
    }
    const float S = s_S;

    // combine u partials over 148 blocks (L2-hot, coalesced over tid)
    {
        float acc = 0.f;
#pragma unroll 4
        for (int b = 0; b < NBLK; b++)
            acc += sf[b] * g_u[b * F + tid];
        sun[tid] = acc / S;
    }
    __syncthreads();

    // h = W_j_w @ u_norm + b : warp-per-row, 32 rows per warp
    const float4 uv = reinterpret_cast<const float4*>(sun)[lane];
#pragma unroll 4
    for (int r = 0; r < 32; r++) {
        const int f = warp * 32 + r;
        const float4 wrow = reinterpret_cast<const float4*>(W_j_w + f * F)[lane];
        float d = wrow.x*uv.x + wrow.y*uv.y + wrow.z*uv.z + wrow.w*uv.w;
#pragma unroll
        for (int off = 16; off > 0; off >>= 1)
            d += __shfl_xor_sync(0xffffffffu, d, off);
        if (lane == 0) {
            const float h = d + W_j_b[f];
            out[f] = (h > 0.f) ? h : expm1f(h);
        }
    }
}

// ---------------------------------------------------------------------------
extern "C" void kernel_launch(void* const* d_in, const int* in_sizes, int n_in,
                              void* d_out, int out_size) {
    const float* h_i   = (const float*)d_in[0];
    const float* h_j   = (const float*)d_in[1];
    const float* W_i_w = (const float*)d_in[2];
    const float* W_i_b = (const float*)d_in[3];
    const float* W_j_w = (const float*)d_in[4];
    const float* W_j_b = (const float*)d_in[5];
    const float* W_ij  = (const float*)d_in[6];
    float* out = (float*)d_out;

    cudaFuncSetAttribute(pass_kernel,
                         cudaFuncAttributeMaxDynamicSharedMemorySize, DYN_SMEM);

    prep_kernel<<<9, 1024>>>(h_i, W_i_w, W_i_b, W_j_w, W_j_b, W_ij);
    pass_kernel<<<NBLK, TPB, DYN_SMEM>>>(h_j, W_j_w, W_j_b, out);
}